// round 17
// baseline (speedup 1.0000x reference)
#include <cuda_runtime.h>
#include <cuda.h>
#include <cstdint>

// ============================================================================
// QuantumNeuralLayer: out = x @ W.T + (b + 0.1*q); q batch-independent.
// 262144x256x64 fp32 GEMM via mma.sync tf32.
// R17: replace cp.async with per-warp TMA (cp.async.bulk.tensor.2d, baseline
// sm_90 PTX). R6-R16 evidence: every SM-side knob (warps/CTAs/ring/order)
// pins at 4.3-4.8 TB/s => per-SM LSU/MSHR request tracking is the wall.
// TMA's dedicated engine bypasses that path: one 4KB box op per warp-stage
// (32 floats x 32 rows, SW128) instead of 256 cp.asyncs. Fragment LDS stays
// conflict-free: all rows a thread touches share r&7 = lane>>2, so SW128
// reduces to one XOR on the 16B-unit index.
// ============================================================================

#define INV_SQRT2 0.70710678118654752440f

static constexpr int B_TOTAL = 262144;
static constexpr int KDIM    = 256;
static constexpr int ODIM    = 64;
static constexpr int TILE_M  = 256;                 // 8 warps x 32 rows
static constexpr int NTILES  = B_TOTAL / TILE_M;    // 1024
static constexpr int NTHREADS = 256;

static constexpr int KCHUNK  = 32;                  // floats per stage
static constexpr int SPT     = KDIM / KCHUNK;       // 8 stages per tile

// SMEM (floats, relative to 1024-aligned base):
//   slots 0..3 : 4 x 8192 floats (32 KB each, SW128 boxes, no padding)
//   Wf         : 16384 floats (64 KB) @ 32768
//   bias       : 64 @ 49152
//   mbars      : 32 x 8 B @ 49216 (as 64 floats)
static constexpr int SLOT_F  = 8192;
static constexpr int WF_F    = 32768;
static constexpr int BIAS_F  = 49152;
static constexpr int MBAR_F  = 49216;
static constexpr int SMEM_F  = 49280;
static constexpr int SMEM_BYTES = SMEM_F * 4 + 1024;   // +1024 align slack

// Bias-prep scratch overlays slot 3 (first TMA into slot 3 happens at j=0,
// after the prologue __syncthreads).
static constexpr int HA_F = 3 * SLOT_F;
static constexpr int HC_F = HA_F + 64;

// ---------------------------------------------------------------------------
__device__ __forceinline__ uint32_t smem_u32(const void* p) {
    uint32_t a;
    asm("{ .reg .u64 t; cvta.to.shared.u64 t, %1; cvt.u32.u64 %0, t; }" : "=r"(a) : "l"(p));
    return a;
}

__device__ __forceinline__ uint32_t f2tf32(float f) {
    uint32_t u;
    asm("cvt.rna.tf32.f32 %0, %1;" : "=r"(u) : "f"(f));
    return u;
}

__device__ __forceinline__ void mma_tf32(float c[4], uint32_t a0, uint32_t a1,
                                         uint32_t a2, uint32_t a3,
                                         uint32_t b0, uint32_t b1) {
    asm volatile(
        "mma.sync.aligned.m16n8k8.row.col.f32.tf32.tf32.f32 "
        "{%0,%1,%2,%3}, {%4,%5,%6,%7}, {%8,%9}, {%0,%1,%2,%3};"
        : "+f"(c[0]), "+f"(c[1]), "+f"(c[2]), "+f"(c[3])
        : "r"(a0), "r"(a1), "r"(a2), "r"(a3), "r"(b0), "r"(b1));
}

__device__ __forceinline__ void mbar_init(uint32_t addr, uint32_t cnt) {
    asm volatile("mbarrier.init.shared.b64 [%0], %1;" :: "r"(addr), "r"(cnt) : "memory");
}
__device__ __forceinline__ void mbar_expect_tx(uint32_t addr, uint32_t bytes) {
    asm volatile("mbarrier.arrive.expect_tx.shared.b64 _, [%0], %1;"
                 :: "r"(addr), "r"(bytes) : "memory");
}
__device__ __forceinline__ void mbar_wait(uint32_t addr, uint32_t parity) {
    asm volatile(
        "{\n\t.reg .pred P;\n\t"
        "W_%=:\n\t"
        "mbarrier.try_wait.parity.acquire.cta.shared::cta.b64 P, [%0], %1, 0x989680;\n\t"
        "@!P bra W_%=;\n\t}"
        :: "r"(addr), "r"(parity) : "memory");
}
__device__ __forceinline__ void tma_load_2d(uint32_t dst, const CUtensorMap* tm,
                                            int cx, int cy, uint32_t mbar) {
    asm volatile(
        "cp.async.bulk.tensor.2d.shared::cta.global.tile.mbarrier::complete_tx::bytes "
        "[%0], [%1, {%2, %3}], [%4];"
        :: "r"(dst), "l"(tm), "r"(cx), "r"(cy), "r"(mbar) : "memory");
}

// ---------------------------------------------------------------------------
__global__ void __launch_bounds__(NTHREADS, 1)
qnl_kernel(const __grid_constant__ CUtensorMap tmap,
           const float* __restrict__ W, const float* __restrict__ bvec,
           const float* __restrict__ phase, const float* __restrict__ ent,
           float* __restrict__ out) {
    extern __shared__ float smem_raw[];
    const uint32_t sb0 = smem_u32(smem_raw);
    const uint32_t sbA = (sb0 + 1023u) & ~1023u;          // SW128-aligned base
    float* smemf = smem_raw + ((sbA - sb0) >> 2);

    const int tid  = threadIdx.x;
    const int wid  = tid >> 5;
    const int lane = tid & 31;
    const int grid = gridDim.x;
    const int bid  = blockIdx.x;

    const int wrow = wid * 32;            // warp's rows [wrow, wrow+32)
    const int q    = lane >> 2;           // fragment row within group, XOR key
    const int c4   = lane & 3;

    const int ntile_local = (NTILES - bid + grid - 1) / grid;
    const int H = SPT * ntile_local;

    // mbar(wid, slot)
    auto mbaddr = [&](int w, int slot) {
        return sbA + (uint32_t)(MBAR_F + (w * 4 + slot) * 2) * 4;
    };

    // Issue one per-warp TMA stage: 4KB box (32 floats x 32 rows) into
    // slot (jq&3) at this warp's 4KB sub-region. lane 0 only.
    const CUtensorMap* tmp = &tmap;
    auto issue_stage = [&](int jq) {
        if (lane == 0) {
            const int slot = jq & 3;
            const int tile = bid + (jq >> 3) * grid;
            const uint32_t mb = mbaddr(wid, slot);
            mbar_expect_tx(mb, 4096u);
            tma_load_2d(sbA + (uint32_t)(slot * SLOT_F + wid * 1024) * 4,
                        tmp, (jq & 7) * KCHUNK, tile * TILE_M + wrow, mb);
        }
    };

    // Init this warp's 4 mbarriers, then prime 3 stages.
    if (lane == 0)
        for (int s = 0; s < 4; s++) mbar_init(mbaddr(wid, s), 1);
    __syncwarp();
    issue_stage(0);
    issue_stage(1);
    issue_stage(2);

    // --- W fragments: tf32-rounded, layout [s(32)][nt(8)][lane(32)] float2 ---
    for (int e = tid; e < 8192; e += NTHREADS) {
        int le = e & 31;
        int nt = (e >> 5) & 7;
        int s  = e >> 8;
        int n = nt * 8 + (le >> 2);
        int k = s * 8 + (le & 3);
        float2 wf;
        wf.x = __uint_as_float(f2tf32(W[n * KDIM + k]));
        wf.y = __uint_as_float(f2tf32(W[n * KDIM + k + 4]));
        *(float2*)(smemf + WF_F + 2 * e) = wf;
    }

    // --- bias_eff = b + 0.1*quantum (scratch overlays slot 3) ---
    {
        float a = 1.0f, c = 0.0f;
        for (int d = 0; d < 3; d++) {
            if (tid < 64) {
                float ph = phase[d * 64 + tid];
                smemf[HA_F + tid] = (a + c) * INV_SQRT2 * sinf(ph);
                smemf[HC_F + tid] = (a - c) * INV_SQRT2 * cosf(ph);
            }
            __syncthreads();
            if (tid < 64) {
                float sa = 0.0f, sc = 0.0f;
#pragma unroll
                for (int i = 0; i < 64; i++) {
                    float e = ent[i * 64 + tid];
                    sa += smemf[HA_F + i] * e;
                    sc += smemf[HC_F + i] * e;
                }
                a = sa; c = sc;
            }
            __syncthreads();
        }
        if (tid < 64) smemf[BIAS_F + tid] = bvec[tid] + 0.1f * (a * a + c * c);
    }
    __syncthreads();   // Wf + bias visible; scratch retired; last CTA barrier

    float2 bias[8];
#pragma unroll
    for (int nt = 0; nt < 8; nt++) {
        int col = nt * 8 + 2 * c4;
        bias[nt].x = smemf[BIAS_F + col];
        bias[nt].y = smemf[BIAS_F + col + 1];
    }

    float acc[2][8][4];
#pragma unroll
    for (int mb = 0; mb < 2; mb++)
#pragma unroll
        for (int nt = 0; nt < 8; nt++)
#pragma unroll
            for (int p = 0; p < 4; p++) acc[mb][nt][p] = 0.0f;

    const float2* Wb = (const float2*)(smemf + WF_F);

    // Per-thread fragment base within a warp region (float index):
    //   B = wid*1024 + q*32 + c4; swizzled col term = 4*(u ^ q), u = k16-unit.
    const int fbase = wid * 1024 + q * 32 + c4;

    for (int j = 0; j < H; j++) {
        if (j + 3 < H) issue_stage(j + 3);   // keep 3 stages in flight

        mbar_wait(mbaddr(wid, j & 3), (j >> 2) & 1);   // stage j resident

        const float* Ab = smemf + (j & 3) * SLOT_F + fbase;
        const int sbase = (j & 7) * 4;

#pragma unroll
        for (int sl = 0; sl < 4; sl++) {
            const int u0 = 4 * ((2 * sl) ^ q);       // swizzled unit offsets
            const int u1 = 4 * ((2 * sl + 1) ^ q);
            uint32_t a0 = f2tf32(Ab[u0]);
            uint32_t a1 = f2tf32(Ab[u0 + 256]);      // row +8  (8*32 floats)
            uint32_t a2 = f2tf32(Ab[u1]);
            uint32_t a3 = f2tf32(Ab[u1 + 256]);
            uint32_t b0 = f2tf32(Ab[u0 + 512]);      // row +16
            uint32_t b1 = f2tf32(Ab[u0 + 768]);      // row +24
            uint32_t b2 = f2tf32(Ab[u1 + 512]);
            uint32_t b3 = f2tf32(Ab[u1 + 768]);
            const int s = sbase + sl;
#pragma unroll
            for (int nt = 0; nt < 8; nt++) {
                float2 wf = Wb[(s * 8 + nt) * 32 + lane];
                uint32_t w0 = __float_as_uint(wf.x);
                uint32_t w1 = __float_as_uint(wf.y);
                mma_tf32(acc[0][nt], a0, a1, a2, a3, w0, w1);
                mma_tf32(acc[1][nt], b0, b1, b2, b3, w0, w1);
            }
        }

        if ((j & 7) == 7) {
            // Tile complete: per-warp epilogue, no barriers.
            const int tile = bid + (j >> 3) * grid;
            const int row0 = tile * TILE_M + wrow + q;
            float* o0 = out + (size_t)row0 * ODIM + 2 * c4;
#pragma unroll
            for (int mb = 0; mb < 2; mb++) {
                float* om = o0 + (size_t)(mb * 16) * ODIM;
#pragma unroll
                for (int nt = 0; nt < 8; nt++) {
                    const int cb = nt * 8;
                    float2 v0 = {acc[mb][nt][0] + bias[nt].x,
                                 acc[mb][nt][1] + bias[nt].y};
                    float2 v1 = {acc[mb][nt][2] + bias[nt].x,
                                 acc[mb][nt][3] + bias[nt].y};
                    *(float2*)(om + cb)            = v0;
                    *(float2*)(om + cb + 8 * ODIM) = v1;
                    acc[mb][nt][0] = acc[mb][nt][1] = 0.0f;
                    acc[mb][nt][2] = acc[mb][nt][3] = 0.0f;
                }
            }
        }
    }
}

// ---------------------------------------------------------------------------
typedef CUresult (*EncodeFn)(CUtensorMap*, CUtensorMapDataType, cuuint32_t,
                             void*, const cuuint64_t*, const cuuint64_t*,
                             const cuuint32_t*, const cuuint32_t*,
                             CUtensorMapInterleave, CUtensorMapSwizzle,
                             CUtensorMapL2promotion, CUtensorMapFloatOOBfill);

extern "C" void kernel_launch(void* const* d_in, const int* in_sizes, int n_in,
                              void* d_out, int out_size) {
    const float* x   = (const float*)d_in[0];
    const float* W   = (const float*)d_in[1];
    const float* b   = (const float*)d_in[2];
    const float* ps  = (const float*)d_in[3];
    const float* ent = (const float*)d_in[4];
    float* out = (float*)d_out;

    static EncodeFn encode = nullptr;
    if (!encode)
        cudaGetDriverEntryPoint("cuTensorMapEncodeTiled", (void**)&encode,
                                cudaEnableDefault);

    CUtensorMap tmap;
    cuuint64_t gdim[2]    = {(cuuint64_t)KDIM, (cuuint64_t)B_TOTAL};
    cuuint64_t gstride[1] = {(cuuint64_t)KDIM * 4};
    cuuint32_t box[2]     = {(cuuint32_t)KCHUNK, 32};     // 128B x 32 rows
    cuuint32_t estride[2] = {1, 1};
    encode(&tmap, CU_TENSOR_MAP_DATA_TYPE_FLOAT32, 2, (void*)x,
           gdim, gstride, box, estride,
           CU_TENSOR_MAP_INTERLEAVE_NONE, CU_TENSOR_MAP_SWIZZLE_128B,
           CU_TENSOR_MAP_L2_PROMOTION_L2_128B,
           CU_TENSOR_MAP_FLOAT_OOB_FILL_NONE);

    cudaFuncSetAttribute(qnl_kernel,
                         cudaFuncAttributeMaxDynamicSharedMemorySize, SMEM_BYTES);

    int sm = 148;
    cudaDeviceGetAttribute(&sm, cudaDevAttrMultiProcessorCount, 0);
    int grid = sm < NTILES ? sm : NTILES;

    qnl_kernel<<<grid, NTHREADS, SMEM_BYTES>>>(tmap, W, b, ps, ent, out);
}